// round 8
// baseline (speedup 1.0000x reference)
#include <cuda_runtime.h>
#include <math.h>

// Problem constants (fixed by setup_inputs)
#define M 16384
#define P 512
#define K 10
#define NMAT 11          // 10 class matrices + 1 global
#define EPSV 0.01f

// ---------------- device scratch (no allocs allowed) ----------------
__device__ __align__(16) float g_A[NMAT * P * P];   // 11.5 MB: raw grams -> B -> L (lower triangle only)
__device__ int g_idx[M];
__device__ int g_cnt[16];
__device__ int g_off[16];
__device__ int g_cur[16];

// ---------------- f32x2 packed FMA helpers (sm_103a) ----------------
__device__ __forceinline__ unsigned long long pack2(float x, float y) {
    unsigned long long r;
    asm("mov.b64 %0, {%1,%2};" : "=l"(r) : "f"(x), "f"(y));
    return r;
}
__device__ __forceinline__ void unpack2(unsigned long long v, float &a, float &b) {
    asm("mov.b64 {%0,%1}, %2;" : "=f"(a), "=f"(b) : "l"(v));
}
__device__ __forceinline__ void ffma2(unsigned long long &d, unsigned long long a, unsigned long long b) {
    asm("fma.rn.f32x2 %0, %1, %2, %0;" : "+l"(d) : "l"(a), "l"(b));
}

// ---------------- zero scratch ----------------
__global__ void zeroA_kernel() {
    int n = NMAT * P * P;
    for (int i = blockIdx.x * blockDim.x + threadIdx.x; i < n; i += gridDim.x * blockDim.x)
        g_A[i] = 0.f;
}

// ---------------- class histogram + offsets ----------------
// NOTE: Y is int32 on device (JAX demotes int64 -> int32 without x64 mode).
__global__ void hist_kernel(const int* __restrict__ Y) {
    __shared__ int h[K];
    int tid = threadIdx.x;
    if (tid < K) h[tid] = 0;
    __syncthreads();
    for (int i = tid; i < M; i += blockDim.x) {
        int c = Y[i];
        if (c >= 0 && c < K) atomicAdd(&h[c], 1);   // bound-checked: never crash on surprise dtype
    }
    __syncthreads();
    if (tid == 0) {
        int acc = 0;
        for (int c = 0; c < K; c++) {
            g_cnt[c] = h[c];
            g_off[c] = acc;
            g_cur[c] = acc;
            acc += h[c];
        }
    }
}

// ---------------- scatter row indices by class ----------------
__global__ void scatter_kernel(const int* __restrict__ Y) {
    for (int i = blockIdx.x * blockDim.x + threadIdx.x; i < M; i += gridDim.x * blockDim.x) {
        int c = Y[i];
        if (c < 0 || c >= K) continue;
        int pos = atomicAdd(&g_cur[c], 1);
        g_idx[pos] = i;
    }
}

// ---------------- per-class SYRK: lower 128x128 tiles, f32x2 FMAs ----------------
#define CH 16   // rows per smem chunk
#define NSPLIT 8

__global__ __launch_bounds__(256) void gram_kernel(const float* __restrict__ X) {
    __shared__ __align__(16) float As[CH][128];
    __shared__ __align__(16) float Bs[CH][128];
    __shared__ int rid[CH];

    const int TI[10] = {0, 1, 1, 2, 2, 2, 3, 3, 3, 3};
    const int TJ[10] = {0, 0, 1, 0, 1, 2, 0, 1, 2, 3};

    int c  = blockIdx.y;
    int ti = TI[blockIdx.x];
    int tj = TJ[blockIdx.x];
    int off = g_off[c], cnt = g_cnt[c];
    int s = blockIdx.z;
    int rbeg = off + (cnt * s) / NSPLIT;
    int rend = off + (cnt * (s + 1)) / NSPLIT;

    int tid = threadIdx.x;
    int tx = tid & 15, ty = tid >> 4;

    unsigned long long acc[8][4];
#pragma unroll
    for (int r = 0; r < 8; r++)
#pragma unroll
        for (int q = 0; q < 4; q++) acc[r][q] = 0ull;

    for (int r0 = rbeg; r0 < rend; r0 += CH) {
        __syncthreads();
        if (tid < CH) rid[tid] = (r0 + tid < rend) ? g_idx[r0 + tid] : -1;
        __syncthreads();
        // load CH rows x (two 128-col slabs), one float4 per thread per array x2
        for (int e = tid; e < CH * 32; e += 256) {
            int rr = e >> 5, f = e & 31;
            int gi = rid[rr];
            float4 va = make_float4(0.f, 0.f, 0.f, 0.f);
            float4 vb = va;
            if (gi >= 0) {
                const float* rp = X + (long long)gi * P;
                va = *(const float4*)(rp + ti * 128 + f * 4);
                vb = *(const float4*)(rp + tj * 128 + f * 4);
            }
            *(float4*)&As[rr][f * 4] = va;
            *(float4*)&Bs[rr][f * 4] = vb;
        }
        __syncthreads();
#pragma unroll
        for (int kk = 0; kk < CH; kk++) {
            float4 a0 = *(const float4*)&As[kk][ty * 8];
            float4 a1 = *(const float4*)&As[kk][ty * 8 + 4];
            ulonglong2 bb0 = *(const ulonglong2*)&Bs[kk][tx * 8];
            ulonglong2 bb1 = *(const ulonglong2*)&Bs[kk][tx * 8 + 4];
            unsigned long long bv[4] = {bb0.x, bb0.y, bb1.x, bb1.y};
            float av[8] = {a0.x, a0.y, a0.z, a0.w, a1.x, a1.y, a1.z, a1.w};
#pragma unroll
            for (int r = 0; r < 8; r++) {
                unsigned long long ar = pack2(av[r], av[r]);
#pragma unroll
                for (int q = 0; q < 4; q++) ffma2(acc[r][q], ar, bv[q]);
            }
        }
    }

    // accumulate into raw class gram (lower triangle only)
    float* Ac = g_A + c * P * P;
    bool dg = (ti == tj);
#pragma unroll
    for (int r = 0; r < 8; r++) {
        int i = ti * 128 + ty * 8 + r;
#pragma unroll
        for (int q = 0; q < 4; q++) {
            float v0, v1;
            unpack2(acc[r][q], v0, v1);
            int j = tj * 128 + tx * 8 + q * 2;
            if (!dg || j <= i)     atomicAdd(&Ac[i * P + j], v0);
            if (!dg || j + 1 <= i) atomicAdd(&Ac[i * P + j + 1], v1);
        }
    }
}

// ---------------- B = I + scal*Gram (lower), B[10] = I + 3.125*sum ----------------
__global__ void assemble_kernel() {
    int e = blockIdx.x * blockDim.x + threadIdx.x;
    if (e >= P * P) return;
    int i = e >> 9, j = e & (P - 1);
    if (j > i) return;
    float add = (i == j) ? 1.f : 0.f;
    float s = 0.f;
#pragma unroll
    for (int c = 0; c < K; c++) {
        float v = g_A[c * P * P + e];
        s += v;
        float trPi = (float)g_cnt[c] + 1e-8f;
        float scal = (float)P / (trPi * EPSV);
        g_A[c * P * P + e] = scal * v + add;
    }
    float scal_g = (float)P / ((float)M * EPSV);   // 3.125
    g_A[K * P * P + e] = scal_g * s + add;
}

// ---------------- Cholesky step: diag factor (64x64) + TRSM panel ----------------
__global__ __launch_bounds__(512) void panel_kernel(int k) {
    __shared__ float Ds[64][65];
    __shared__ float inv[64];
    int c = blockIdx.x;
    float* A = g_A + c * P * P;
    int kb = k * 64;
    int tid = threadIdx.x;

    for (int e = tid; e < 4096; e += 512) {
        int i = e >> 6, j = e & 63;
        Ds[i][j] = (j <= i) ? A[(kb + i) * P + kb + j] : 0.f;
    }
    // unnormalized outer-product factorization: one sync per column
    for (int j = 0; j < 64; j++) {
        __syncthreads();
        float invd = 1.0f / Ds[j][j];
        for (int i = j + 1 + (tid >> 4); i < 64; i += 32) {
            float cij = Ds[i][j] * invd;
            for (int t = j + 1 + (tid & 15); t <= i; t += 16)
                Ds[i][t] -= cij * Ds[t][j];
        }
    }
    __syncthreads();
    if (tid < 64) inv[tid] = rsqrtf(Ds[tid][tid]);
    __syncthreads();
    for (int e = tid; e < 4096; e += 512) {
        int i = e >> 6, j = e & 63;
        if (j <= i) Ds[i][j] *= inv[j];   // L = C * diag(rsqrt(d)); L[j][j]=sqrt(d), inv[j]=1/L[j][j]
    }
    __syncthreads();
    for (int e = tid; e < 4096; e += 512) {
        int i = e >> 6, j = e & 63;
        if (j <= i) A[(kb + i) * P + kb + j] = Ds[i][j];
    }
    // TRSM: one row per thread, w[] in registers, fully unrolled forward substitution
    int row = kb + 64 + tid;
    if (row < P) {
        float w[64];
        const float* rp = A + (long long)row * P + kb;
#pragma unroll
        for (int q = 0; q < 16; q++) {
            float4 v = *(const float4*)(rp + q * 4);
            w[q * 4] = v.x; w[q * 4 + 1] = v.y; w[q * 4 + 2] = v.z; w[q * 4 + 3] = v.w;
        }
#pragma unroll
        for (int j = 0; j < 64; j++) {
            float xj = w[j] * inv[j];
            w[j] = xj;
#pragma unroll
            for (int t = j + 1; t < 64; t++) w[t] -= xj * Ds[t][j];
        }
        float* wp = A + (long long)row * P + kb;
#pragma unroll
        for (int q = 0; q < 16; q++) {
            float4 v = make_float4(w[q * 4], w[q * 4 + 1], w[q * 4 + 2], w[q * 4 + 3]);
            *(float4*)(wp + q * 4) = v;
        }
    }
}

// ---------------- trailing SYRK update (lower tiles) ----------------
__global__ __launch_bounds__(256) void syrk_kernel(int k) {
    __shared__ float PiT[64][65];
    __shared__ float PjT[64][65];
    int c = blockIdx.y;
    float* A = g_A + c * P * P;
    int kb = k * 64;

    int l = blockIdx.x;
    int bi = 0;
    while (l >= bi + 1) { l -= bi + 1; bi++; }
    int bj = l;
    int I = kb + 64 + bi * 64;
    int J = kb + 64 + bj * 64;

    int tid = threadIdx.x;
    for (int e = tid; e < 4096; e += 256) {
        int r = e >> 6, t = e & 63;
        PiT[t][r] = A[(I + r) * P + kb + t];
        PjT[t][r] = A[(J + r) * P + kb + t];
    }
    __syncthreads();

    int tx = tid & 15, ty = tid >> 4;
    float acc[4][4];
#pragma unroll
    for (int r = 0; r < 4; r++)
#pragma unroll
        for (int s = 0; s < 4; s++) acc[r][s] = 0.f;

#pragma unroll 4
    for (int t = 0; t < 64; t++) {
        float a[4], b[4];
#pragma unroll
        for (int r = 0; r < 4; r++) a[r] = PiT[t][ty * 4 + r];
#pragma unroll
        for (int s = 0; s < 4; s++) b[s] = PjT[t][tx * 4 + s];
#pragma unroll
        for (int r = 0; r < 4; r++)
#pragma unroll
            for (int s = 0; s < 4; s++) acc[r][s] += a[r] * b[s];
    }

    bool dg = (bi == bj);
#pragma unroll
    for (int r = 0; r < 4; r++) {
        int li = ty * 4 + r;
#pragma unroll
        for (int s = 0; s < 4; s++) {
            int lj = tx * 4 + s;
            if (!dg || lj <= li)
                A[(I + li) * P + J + lj] -= acc[r][s];
        }
    }
}

// ---------------- final: logdet from diag(L), weighted sums ----------------
__global__ void final_kernel(float* out) {
    __shared__ float red[512];
    __shared__ float sums[NMAT];
    int tid = threadIdx.x;
    for (int c = 0; c < NMAT; c++) {
        red[tid] = logf(g_A[c * P * P + tid * P + tid]);
        __syncthreads();
        for (int s = 256; s > 0; s >>= 1) {
            if (tid < s) red[tid] += red[tid + s];
            __syncthreads();
        }
        if (tid == 0) sums[c] = red[0];
        __syncthreads();
    }
    if (tid == 0) {
        // discrimn = logdet/2 = sum(log diag L);  compress = sum_c (2*sumlog_c)*trPi_c/m/2
        float comp = 0.f;
        for (int c = 0; c < K; c++) {
            float trPi = (float)g_cnt[c] + 1e-8f;
            comp += sums[c] * trPi / (float)M;
        }
        out[0] = sums[K];
        out[1] = comp;
    }
}

// ---------------- launch ----------------
extern "C" void kernel_launch(void* const* d_in, const int* in_sizes, int n_in,
                              void* d_out, int out_size) {
    const float* X = (const float*)d_in[0];
    const int* Y = (const int*)d_in[1];   // int32: JAX demotes int64 without x64 mode
    float* out = (float*)d_out;

    zeroA_kernel<<<2048, 256>>>();
    hist_kernel<<<1, 256>>>(Y);
    scatter_kernel<<<64, 256>>>(Y);
    gram_kernel<<<dim3(10, K, NSPLIT), 256>>>(X);
    assemble_kernel<<<(P * P + 255) / 256, 256>>>();
    for (int k = 0; k < 8; k++) {
        panel_kernel<<<NMAT, 512>>>(k);
        int nt = 7 - k;
        if (nt > 0)
            syrk_kernel<<<dim3(nt * (nt + 1) / 2, NMAT), 256>>>(k);
    }
    final_kernel<<<1, 512>>>(out);
}